// round 3
// baseline (speedup 1.0000x reference)
#include <cuda_runtime.h>
#include <math.h>

#define DM 1024      // D_MODEL
#define DI 2048      // D_INNER
#define DS 16        // D_STATE
#define DC 4         // D_CONV
#define NB 2         // batch
#define TT 1024      // seq len
#define MR (NB*TT)   // 2048 rows
#define NP (2*DS+1)  // 33 ssm projection width

// ---------------- scratch (device globals; no allocations allowed) ----------
static __device__ float g_xn  [MR*DM];        // 8 MB
static __device__ float g_xz  [MR*2*DI];      // 32 MB
static __device__ float g_xc  [MR*DI];        // 16 MB
static __device__ float g_ssmp[MR*NP];        // 264 KB
static __device__ float g_dt  [MR*DI];        // 16 MB
static __device__ float g_y   [MR*DI];        // 16 MB

// ---------------- LayerNorm: one block per row ------------------------------
__global__ __launch_bounds__(256) void ln_kernel(
    const float* __restrict__ x, const float* __restrict__ gamma,
    const float* __restrict__ beta)
{
    int row = blockIdx.x;
    int tid = threadIdx.x;
    const float4* xr = (const float4*)(x + (size_t)row * DM);
    float4 v = xr[tid];
    float s = v.x + v.y + v.z + v.w;
    float q = v.x*v.x + v.y*v.y + v.z*v.z + v.w*v.w;
    #pragma unroll
    for (int o = 16; o; o >>= 1) {
        s += __shfl_down_sync(0xFFFFFFFFu, s, o);
        q += __shfl_down_sync(0xFFFFFFFFu, q, o);
    }
    __shared__ float ss[8], sq[8];
    __shared__ float mu_s, rs_s;
    if ((tid & 31) == 0) { ss[tid >> 5] = s; sq[tid >> 5] = q; }
    __syncthreads();
    if (tid == 0) {
        float S = 0.f, Q = 0.f;
        #pragma unroll
        for (int i = 0; i < 8; i++) { S += ss[i]; Q += sq[i]; }
        float mu  = S / (float)DM;
        float var = Q / (float)DM - mu * mu;
        mu_s = mu;
        rs_s = rsqrtf(var + 1e-5f);
    }
    __syncthreads();
    float mu = mu_s, rs = rs_s;
    float4 g = ((const float4*)gamma)[tid];
    float4 b = ((const float4*)beta)[tid];
    float4 o;
    o.x = (v.x - mu) * rs * g.x + b.x;
    o.y = (v.y - mu) * rs * g.y + b.y;
    o.z = (v.z - mu) * rs * g.z + b.z;
    o.w = (v.w - mu) * rs * g.w + b.w;
    ((float4*)(g_xn + (size_t)row * DM))[tid] = o;
}

// ---------------- SGEMM NT: C[m][n] = sum_k A[m,k]*B[n,k] (+Cadd) -----------
// 128x128 tile, BK=8, 256 threads, 8x8 per thread in 2x2 segments of 4
// (segment split keeps the float4 shared loads bank-conflict free).
__global__ __launch_bounds__(256) void sgemm_nt(
    const float* __restrict__ A, const float* __restrict__ B,
    const float* __restrict__ Cadd, float* __restrict__ C,
    int M, int N, int K)
{
    __shared__ float As[8][128];
    __shared__ float Bs[8][128];
    int tid = threadIdx.x;
    int bm = blockIdx.y * 128, bn = blockIdx.x * 128;
    int lr = tid >> 1;          // 0..127 tile row for loading
    int lk = (tid & 1) * 4;     // 0 or 4
    int tx = tid & 15, ty = tid >> 4;

    const float* Ap = A + (size_t)(bm + lr) * K + lk;
    const float* Bp = B + (size_t)(bn + lr) * K + lk;

    float acc[8][8];
    #pragma unroll
    for (int i = 0; i < 8; i++)
        #pragma unroll
        for (int j = 0; j < 8; j++) acc[i][j] = 0.f;

    for (int k0 = 0; k0 < K; k0 += 8) {
        float4 a = *(const float4*)(Ap + k0);
        float4 b = *(const float4*)(Bp + k0);
        As[lk+0][lr] = a.x; As[lk+1][lr] = a.y; As[lk+2][lr] = a.z; As[lk+3][lr] = a.w;
        Bs[lk+0][lr] = b.x; Bs[lk+1][lr] = b.y; Bs[lk+2][lr] = b.z; Bs[lk+3][lr] = b.w;
        __syncthreads();
        #pragma unroll
        for (int k = 0; k < 8; k++) {
            float4 a0 = *(const float4*)&As[k][ty*4];
            float4 a1 = *(const float4*)&As[k][ty*4 + 64];
            float4 b0 = *(const float4*)&Bs[k][tx*4];
            float4 b1 = *(const float4*)&Bs[k][tx*4 + 64];
            float ra[8] = {a0.x,a0.y,a0.z,a0.w,a1.x,a1.y,a1.z,a1.w};
            float rb[8] = {b0.x,b0.y,b0.z,b0.w,b1.x,b1.y,b1.z,b1.w};
            #pragma unroll
            for (int i = 0; i < 8; i++)
                #pragma unroll
                for (int j = 0; j < 8; j++)
                    acc[i][j] += ra[i] * rb[j];
        }
        __syncthreads();
    }

    #pragma unroll
    for (int si = 0; si < 2; si++) {
        #pragma unroll
        for (int ii = 0; ii < 4; ii++) {
            int m = bm + si*64 + ty*4 + ii;
            #pragma unroll
            for (int sj = 0; sj < 2; sj++) {
                int ncol = bn + sj*64 + tx*4;
                float4 o;
                o.x = acc[si*4+ii][sj*4+0];
                o.y = acc[si*4+ii][sj*4+1];
                o.z = acc[si*4+ii][sj*4+2];
                o.w = acc[si*4+ii][sj*4+3];
                if (Cadd) {
                    float4 c = *(const float4*)(Cadd + (size_t)m*N + ncol);
                    o.x += c.x; o.y += c.y; o.z += c.z; o.w += c.w;
                }
                *(float4*)(C + (size_t)m*N + ncol) = o;
            }
        }
    }
}

// ---------------- causal depthwise conv (k=4) + bias + SiLU -----------------
__global__ __launch_bounds__(256) void conv_silu_kernel(
    const float* __restrict__ cw, const float* __restrict__ cb)
{
    int idx = blockIdx.x * 256 + threadIdx.x;   // over MR*DI
    int d = idx & (DI - 1);
    int row = idx >> 11;                        // /DI
    int t = row & (TT - 1);
    const float* xb = g_xz + (size_t)row * (2*DI) + d;
    float w0 = cw[d*4+0], w1 = cw[d*4+1], w2 = cw[d*4+2], w3 = cw[d*4+3];
    float acc = cb[d] + w3 * xb[0];
    if (t >= 1) acc += w2 * xb[-(ptrdiff_t)(2*DI)];
    if (t >= 2) acc += w1 * xb[-(ptrdiff_t)(4*DI)];
    if (t >= 3) acc += w0 * xb[-(ptrdiff_t)(6*DI)];
    acc = acc / (1.f + expf(-acc));   // silu
    g_xc[idx] = acc;
}

// ---------------- ssm_p = xc @ W_x.T  (N=33), 2 rows per block --------------
__global__ __launch_bounds__(256) void proj_kernel(const float* __restrict__ Wx)
{
    int row0 = blockIdx.x * 2;
    const float* x0 = g_xc + (size_t)row0 * DI;
    const float* x1 = x0 + DI;
    float a0[NP], a1[NP];
    #pragma unroll
    for (int n = 0; n < NP; n++) { a0[n] = 0.f; a1[n] = 0.f; }
    for (int k = threadIdx.x; k < DI; k += 256) {
        float v0 = x0[k], v1 = x1[k];
        #pragma unroll
        for (int n = 0; n < NP; n++) {
            float wv = Wx[(size_t)n * DI + k];
            a0[n] += v0 * wv;
            a1[n] += v1 * wv;
        }
    }
    #pragma unroll
    for (int n = 0; n < NP; n++) {
        #pragma unroll
        for (int o = 16; o; o >>= 1) {
            a0[n] += __shfl_down_sync(0xFFFFFFFFu, a0[n], o);
            a1[n] += __shfl_down_sync(0xFFFFFFFFu, a1[n], o);
        }
    }
    __shared__ float red0[8][NP], red1[8][NP];
    int w = threadIdx.x >> 5, l = threadIdx.x & 31;
    if (l == 0) {
        #pragma unroll
        for (int n = 0; n < NP; n++) { red0[w][n] = a0[n]; red1[w][n] = a1[n]; }
    }
    __syncthreads();
    if (threadIdx.x < NP) {
        float s0 = 0.f, s1 = 0.f;
        #pragma unroll
        for (int ww = 0; ww < 8; ww++) { s0 += red0[ww][threadIdx.x]; s1 += red1[ww][threadIdx.x]; }
        g_ssmp[(size_t)row0 * NP + threadIdx.x] = s0;
        g_ssmp[(size_t)(row0+1) * NP + threadIdx.x] = s1;
    }
}

// ---------------- dt = softplus(dt_raw * w_dt + b_dt) -----------------------
__global__ __launch_bounds__(256) void dt_kernel(
    const float* __restrict__ w_dt, const float* __restrict__ b_dt)
{
    int idx = blockIdx.x * 256 + threadIdx.x;   // over MR*DI
    int d = idx & (DI - 1);
    int row = idx >> 11;
    float v = g_ssmp[(size_t)row * NP] * w_dt[d] + b_dt[d];
    g_dt[idx] = (v > 20.f) ? v : log1pf(expf(v));
}

// ---------------- selective scan: 16 lanes per channel, seq over T ----------
// also fuses y = (scan + D*xc) * silu(z)
__global__ __launch_bounds__(256) void scan_kernel(
    const float* __restrict__ A_log, const float* __restrict__ D_param)
{
    int tid  = threadIdx.x;
    int w    = tid >> 5;
    int lane = tid & 31;
    int grp  = lane >> 4;       // which of 2 channels in this warp
    int n    = lane & 15;       // state index
    int ch   = blockIdx.x * 16 + w * 2 + grp;   // 0..4095
    int b    = ch >> 11;        // /DI
    int d    = ch & (DI - 1);

    float An = -expf(A_log[d * DS + n]);
    float Dp = D_param[d];

    const float* sp  = g_ssmp + (size_t)b * TT * NP;
    const float* dtp = g_dt   + (size_t)b * TT * DI + d;
    const float* xp  = g_xc   + (size_t)b * TT * DI + d;
    const float* zp  = g_xz   + (size_t)b * TT * (2*DI) + DI + d;
    float*       yp  = g_y    + (size_t)b * TT * DI + d;

    float h = 0.f;
    // prefetch t=0
    float Bn  = sp[1 + n];
    float Cn  = sp[17 + n];
    float dtv = dtp[0];
    float xv  = xp[0];

    for (int t = 0; t < TT; t++) {
        float Bn2 = 0.f, Cn2 = 0.f, dt2 = 0.f, x2 = 0.f;
        if (t + 1 < TT) {
            Bn2 = sp[(size_t)(t+1)*NP + 1 + n];
            Cn2 = sp[(size_t)(t+1)*NP + 17 + n];
            dt2 = dtp[(size_t)(t+1)*DI];
            x2  = xp [(size_t)(t+1)*DI];
        }
        float ab = __expf(dtv * An);
        h = ab * h + (dtv * xv) * Bn;
        float p = h * Cn;
        p += __shfl_xor_sync(0xFFFFFFFFu, p, 1);
        p += __shfl_xor_sync(0xFFFFFFFFu, p, 2);
        p += __shfl_xor_sync(0xFFFFFFFFu, p, 4);
        p += __shfl_xor_sync(0xFFFFFFFFu, p, 8);
        if (n == 0) {
            float zv = zp[(size_t)t * (2*DI)];
            float yv = p + Dp * xv;
            yv *= zv / (1.f + __expf(-zv));
            yp[(size_t)t * DI] = yv;
        }
        Bn = Bn2; Cn = Cn2; dtv = dt2; xv = x2;
    }
}

// ---------------- launch ----------------------------------------------------
extern "C" void kernel_launch(void* const* d_in, const int* in_sizes, int n_in,
                              void* d_out, int out_size)
{
    const float* x       = (const float*)d_in[0];
    const float* ln_g    = (const float*)d_in[1];
    const float* ln_b    = (const float*)d_in[2];
    const float* W_in    = (const float*)d_in[3];
    const float* conv_w  = (const float*)d_in[4];
    const float* conv_b  = (const float*)d_in[5];
    const float* W_x     = (const float*)d_in[6];
    const float* w_dt    = (const float*)d_in[7];
    const float* b_dt    = (const float*)d_in[8];
    const float* A_log   = (const float*)d_in[9];
    const float* D_param = (const float*)d_in[10];
    const float* W_out   = (const float*)d_in[11];
    float* out = (float*)d_out;

    float *xn, *xz, *y;
    cudaGetSymbolAddress((void**)&xn, g_xn);
    cudaGetSymbolAddress((void**)&xz, g_xz);
    cudaGetSymbolAddress((void**)&y,  g_y);

    // 1) layernorm
    ln_kernel<<<MR, 256>>>(x, ln_g, ln_b);

    // 2) xz = xn @ W_in.T   (M=2048, N=4096, K=1024)
    {
        dim3 grid(4096/128, 2048/128);
        sgemm_nt<<<grid, 256>>>(xn, W_in, nullptr, xz, MR, 2*DI, DM);
    }

    // 3) causal conv + silu -> xc
    conv_silu_kernel<<<(MR*DI)/256, 256>>>(conv_w, conv_b);

    // 4) ssm_p = xc @ W_x.T
    proj_kernel<<<MR/2, 256>>>(W_x);

    // 5) dt = softplus(...)
    dt_kernel<<<(MR*DI)/256, 256>>>(w_dt, b_dt);

    // 6) selective scan -> g_y (gated)
    scan_kernel<<<(NB*DI)/16, 256>>>(A_log, D_param);

    // 7) out = x + y @ W_out.T   (M=2048, N=1024, K=2048)
    {
        dim3 grid(1024/128, 2048/128);
        sgemm_nt<<<grid, 256>>>(y, W_out, x, out, MR, DM, DI);
    }
}

// round 6
// speedup vs baseline: 1.8820x; 1.8820x over previous
#include <cuda_runtime.h>
#include <cuda_bf16.h>
#include <math.h>
#include <stdint.h>

#define DM 1024      // D_MODEL
#define DI 2048      // D_INNER
#define DS 16        // D_STATE
#define NB 2         // batch
#define TT 1024      // seq len
#define MR (NB*TT)   // 2048 rows
#define NP (2*DS+1)  // 33

// ---------------- scratch (device globals; no allocations allowed) ----------
static __device__ float g_xz  [MR*2*DI];         // 32 MB fp32 (conv + z gate)
static __device__ float g_xc  [MR*DI];           // 16 MB
static __device__ float g_ssmp[MR*NP];
static __device__ float g_dt  [MR*DI];
static __device__ __nv_bfloat16 g_xnb [MR*DM];   // LN output, bf16 (GEMM1 A)
static __device__ __nv_bfloat16 g_winb[2*DI*DM]; // W_in bf16   (GEMM1 B)
static __device__ __nv_bfloat16 g_ybf [MR*DI];   // scan output bf16 (GEMM2 A)
static __device__ __nv_bfloat16 g_woutb[DM*DI];  // W_out bf16  (GEMM2 B)

__device__ __forceinline__ uint32_t smem_to_u32(const void* p) {
    uint32_t a;
    asm("{ .reg .u64 t; cvta.to.shared.u64 t, %1; cvt.u32.u64 %0, t; }"
        : "=r"(a) : "l"(p));
    return a;
}
// SW128-style swizzle on (row*128 + chunk*16) byte offsets
#define SWZ128(x) ((x) ^ (((x) >> 3) & 0x70))

// =================== bf16 mma.sync GEMM NT: C = A @ B^T (+Cadd) =============
// A[M,K] bf16 row-major, B[N,K] bf16 row-major, C[M,N] fp32.
// CTA tile 128x128, BK=64 (128B rows, swizzled), double-buffered cp.async.
// 8 warps (2 M x 4 N), warp tile 64x32, m16n8k16 bf16 MMA, fp32 accum.
#define GEMM_SMEM_BYTES (2 * 2 * 16384)   // 2 buffers x (A 16KB + B 16KB)

__global__ __launch_bounds__(256)
void gemm_bf16_mma(const __nv_bfloat16* __restrict__ A,
                   const __nv_bfloat16* __restrict__ B,
                   const float* __restrict__ Cadd, float* __restrict__ C,
                   int N, int K)
{
    extern __shared__ char dsm[];
    uint32_t sb = smem_to_u32(dsm);
    const int tid = threadIdx.x, wid = tid >> 5, lane = tid & 31;
    const int bm = blockIdx.y * 128, bn = blockIdx.x * 128;
    const int wm = wid >> 2, wn = wid & 3;        // warp grid 2x4
    const int mbase = wm * 64, nbase = wn * 32;   // within tile

    const char* Ab = (const char*)A;
    const char* Bb = (const char*)B;
    const size_t K2 = (size_t)K * 2;
    const int KC = K >> 6;                        // 64-k chunks

    // per-thread cp.async staging pattern: 8 chunks of 16B
    // i = tid + it*256 over 2048: [0,1024)=A, [1024,2048)=B
    // row = (i&1023)>>3, sub = i&7
    // ldmatrix address components
    const int a_row = lane & 15;          // A: row within 16-row frag
    const int a_kc  = lane >> 4;          // A: 16B chunk select (0/1)
    const int b_row = ((lane >> 4) << 3) + (lane & 7);  // B: n row within 32
    const int b_kc  = (lane >> 3) & 1;

    float d[4][4][4];
    #pragma unroll
    for (int i = 0; i < 4; i++)
        #pragma unroll
        for (int j = 0; j < 4; j++)
            { d[i][j][0]=0.f; d[i][j][1]=0.f; d[i][j][2]=0.f; d[i][j][3]=0.f; }

    // ---- prefetch chunk 0 into buffer 0 ----
    #pragma unroll
    for (int it = 0; it < 8; it++) {
        int i = tid + it * 256;
        int isB = i >> 10;
        int j = i & 1023;
        int row = j >> 3, sub = j & 7;
        const char* src = (isB ? Bb + (size_t)(bn + row) * K2
                               : Ab + (size_t)(bm + row) * K2) + sub * 16;
        uint32_t dst = sb + isB * 16384 + SWZ128(row * 128 + sub * 16);
        asm volatile("cp.async.cg.shared.global [%0], [%1], 16;\n" :: "r"(dst), "l"(src));
    }
    asm volatile("cp.async.commit_group;\n" ::: "memory");

    for (int kc = 0; kc < KC; kc++) {
        int cur = kc & 1;
        // prefetch next chunk into other buffer
        if (kc + 1 < KC) {
            int nxt = (kc + 1) & 1;
            #pragma unroll
            for (int it = 0; it < 8; it++) {
                int i = tid + it * 256;
                int isB = i >> 10;
                int j = i & 1023;
                int row = j >> 3, sub = j & 7;
                const char* src = (isB ? Bb + (size_t)(bn + row) * K2
                                       : Ab + (size_t)(bm + row) * K2)
                                  + (size_t)(kc + 1) * 128 + sub * 16;
                uint32_t dst = sb + nxt * 32768 + isB * 16384
                             + SWZ128(row * 128 + sub * 16);
                asm volatile("cp.async.cg.shared.global [%0], [%1], 16;\n" :: "r"(dst), "l"(src));
            }
            asm volatile("cp.async.commit_group;\n" ::: "memory");
            asm volatile("cp.async.wait_group 1;\n" ::: "memory");
        } else {
            asm volatile("cp.async.wait_group 0;\n" ::: "memory");
        }
        __syncthreads();

        uint32_t sA = sb + cur * 32768;
        uint32_t sB = sA + 16384;

        #pragma unroll
        for (int ks = 0; ks < 4; ks++) {          // 4 x k16 within the 64-k chunk
            uint32_t a[4][4], b[4][2];
            #pragma unroll
            for (int mf = 0; mf < 4; mf++) {
                uint32_t addr = sA + SWZ128((mbase + mf*16 + a_row) * 128
                                            + (ks*2 + a_kc) * 16);
                asm volatile("ldmatrix.sync.aligned.m8n8.x4.shared.b16 {%0,%1,%2,%3}, [%4];"
                    : "=r"(a[mf][0]), "=r"(a[mf][1]), "=r"(a[mf][2]), "=r"(a[mf][3])
                    : "r"(addr));
            }
            #pragma unroll
            for (int nb2 = 0; nb2 < 2; nb2++) {   // two x4 loads cover 4 n8-frags
                uint32_t addr = sB + SWZ128((nbase + nb2*16 + b_row) * 128
                                            + (ks*2 + b_kc) * 16);
                asm volatile("ldmatrix.sync.aligned.m8n8.x4.shared.b16 {%0,%1,%2,%3}, [%4];"
                    : "=r"(b[nb2*2][0]), "=r"(b[nb2*2][1]),
                      "=r"(b[nb2*2+1][0]), "=r"(b[nb2*2+1][1])
                    : "r"(addr));
            }
            #pragma unroll
            for (int mf = 0; mf < 4; mf++)
                #pragma unroll
                for (int nf = 0; nf < 4; nf++) {
                    asm volatile(
                        "mma.sync.aligned.m16n8k16.row.col.f32.bf16.bf16.f32 "
                        "{%0,%1,%2,%3}, {%4,%5,%6,%7}, {%8,%9}, {%0,%1,%2,%3};"
                        : "+f"(d[mf][nf][0]), "+f"(d[mf][nf][1]),
                          "+f"(d[mf][nf][2]), "+f"(d[mf][nf][3])
                        : "r"(a[mf][0]), "r"(a[mf][1]), "r"(a[mf][2]), "r"(a[mf][3]),
                          "r"(b[nf][0]), "r"(b[nf][1]));
                }
        }
        __syncthreads();
    }

    // ---- epilogue: fp32 accums -> C (+Cadd), each thread 2 floats per frag row
    const int er = lane >> 2;          // 0..7 row within 8
    const int ec = (lane & 3) * 2;     // col pair
    #pragma unroll
    for (int mf = 0; mf < 4; mf++) {
        int m0 = bm + mbase + mf*16 + er;
        #pragma unroll
        for (int nf = 0; nf < 4; nf++) {
            int col = bn + nbase + nf*8 + ec;
            float2 v0 = make_float2(d[mf][nf][0], d[mf][nf][1]);
            float2 v1 = make_float2(d[mf][nf][2], d[mf][nf][3]);
            if (Cadd) {
                float2 c0 = *(const float2*)(Cadd + (size_t)m0 * N + col);
                float2 c1 = *(const float2*)(Cadd + (size_t)(m0+8) * N + col);
                v0.x += c0.x; v0.y += c0.y; v1.x += c1.x; v1.y += c1.y;
            }
            *(float2*)(C + (size_t)m0 * N + col) = v0;
            *(float2*)(C + (size_t)(m0+8) * N + col) = v1;
        }
    }
}

// ---------------- fp32 -> bf16 convert (vectorized x4) ----------------------
__global__ __launch_bounds__(256) void f2bf4(
    const float* __restrict__ in, __nv_bfloat16* __restrict__ out, int n4)
{
    int i = blockIdx.x * 256 + threadIdx.x;
    if (i >= n4) return;
    float4 v = ((const float4*)in)[i];
    ((__nv_bfloat162*)out)[i*2+0] = __floats2bfloat162_rn(v.x, v.y);
    ((__nv_bfloat162*)out)[i*2+1] = __floats2bfloat162_rn(v.z, v.w);
}

// ---------------- LayerNorm: one block per row, bf16 output -----------------
__global__ __launch_bounds__(256) void ln_kernel(
    const float* __restrict__ x, const float* __restrict__ gamma,
    const float* __restrict__ beta)
{
    int row = blockIdx.x;
    int tid = threadIdx.x;
    const float4* xr = (const float4*)(x + (size_t)row * DM);
    float4 v = xr[tid];
    float s = v.x + v.y + v.z + v.w;
    float q = v.x*v.x + v.y*v.y + v.z*v.z + v.w*v.w;
    #pragma unroll
    for (int o = 16; o; o >>= 1) {
        s += __shfl_down_sync(0xFFFFFFFFu, s, o);
        q += __shfl_down_sync(0xFFFFFFFFu, q, o);
    }
    __shared__ float ss[8], sq[8];
    __shared__ float mu_s, rs_s;
    if ((tid & 31) == 0) { ss[tid >> 5] = s; sq[tid >> 5] = q; }
    __syncthreads();
    if (tid == 0) {
        float S = 0.f, Q = 0.f;
        #pragma unroll
        for (int i = 0; i < 8; i++) { S += ss[i]; Q += sq[i]; }
        float mu  = S / (float)DM;
        float var = Q / (float)DM - mu * mu;
        mu_s = mu;
        rs_s = rsqrtf(var + 1e-5f);
    }
    __syncthreads();
    float mu = mu_s, rs = rs_s;
    float4 g = ((const float4*)gamma)[tid];
    float4 b = ((const float4*)beta)[tid];
    float ox = (v.x - mu) * rs * g.x + b.x;
    float oy = (v.y - mu) * rs * g.y + b.y;
    float oz = (v.z - mu) * rs * g.z + b.z;
    float ow = (v.w - mu) * rs * g.w + b.w;
    __nv_bfloat162* o2 = (__nv_bfloat162*)(g_xnb + (size_t)row * DM);
    o2[tid*2+0] = __floats2bfloat162_rn(ox, oy);
    o2[tid*2+1] = __floats2bfloat162_rn(oz, ow);
}

// ---------------- causal depthwise conv (k=4) + bias + SiLU -----------------
__global__ __launch_bounds__(256) void conv_silu_kernel(
    const float* __restrict__ cw, const float* __restrict__ cb)
{
    int idx = blockIdx.x * 256 + threadIdx.x;   // over MR*DI
    int d = idx & (DI - 1);
    int row = idx >> 11;                        // /DI
    int t = row & (TT - 1);
    const float* xb = g_xz + (size_t)row * (2*DI) + d;
    float w0 = cw[d*4+0], w1 = cw[d*4+1], w2 = cw[d*4+2], w3 = cw[d*4+3];
    float acc = cb[d] + w3 * xb[0];
    if (t >= 1) acc += w2 * xb[-(ptrdiff_t)(2*DI)];
    if (t >= 2) acc += w1 * xb[-(ptrdiff_t)(4*DI)];
    if (t >= 3) acc += w0 * xb[-(ptrdiff_t)(6*DI)];
    acc = acc / (1.f + expf(-acc));   // silu
    g_xc[idx] = acc;
}

// ---------------- ssm_p = xc @ W_x.T  (N=33), 2 rows per block --------------
__global__ __launch_bounds__(256) void proj_kernel(const float* __restrict__ Wx)
{
    int row0 = blockIdx.x * 2;
    const float* x0 = g_xc + (size_t)row0 * DI;
    const float* x1 = x0 + DI;
    float a0[NP], a1[NP];
    #pragma unroll
    for (int n = 0; n < NP; n++) { a0[n] = 0.f; a1[n] = 0.f; }
    for (int k = threadIdx.x; k < DI; k += 256) {
        float v0 = x0[k], v1 = x1[k];
        #pragma unroll
        for (int n = 0; n < NP; n++) {
            float wv = Wx[(size_t)n * DI + k];
            a0[n] += v0 * wv;
            a1[n] += v1 * wv;
        }
    }
    #pragma unroll
    for (int n = 0; n < NP; n++) {
        #pragma unroll
        for (int o = 16; o; o >>= 1) {
            a0[n] += __shfl_down_sync(0xFFFFFFFFu, a0[n], o);
            a1[n] += __shfl_down_sync(0xFFFFFFFFu, a1[n], o);
        }
    }
    __shared__ float red0[8][NP], red1[8][NP];
    int w = threadIdx.x >> 5, l = threadIdx.x & 31;
    if (l == 0) {
        #pragma unroll
        for (int n = 0; n < NP; n++) { red0[w][n] = a0[n]; red1[w][n] = a1[n]; }
    }
    __syncthreads();
    if (threadIdx.x < NP) {
        float s0 = 0.f, s1 = 0.f;
        #pragma unroll
        for (int ww = 0; ww < 8; ww++) { s0 += red0[ww][threadIdx.x]; s1 += red1[ww][threadIdx.x]; }
        g_ssmp[(size_t)row0 * NP + threadIdx.x] = s0;
        g_ssmp[(size_t)(row0+1) * NP + threadIdx.x] = s1;
    }
}

// ---------------- dt = softplus(dt_raw * w_dt + b_dt) -----------------------
__global__ __launch_bounds__(256) void dt_kernel(
    const float* __restrict__ w_dt, const float* __restrict__ b_dt)
{
    int idx = blockIdx.x * 256 + threadIdx.x;   // over MR*DI
    int d = idx & (DI - 1);
    int row = idx >> 11;
    float v = g_ssmp[(size_t)row * NP] * w_dt[d] + b_dt[d];
    g_dt[idx] = (v > 20.f) ? v : log1pf(expf(v));
}

// ---------------- selective scan: 16 lanes per channel, seq over T ----------
// fuses y = (scan + D*xc) * silu(z), writes bf16 for GEMM2
__global__ __launch_bounds__(256) void scan_kernel(
    const float* __restrict__ A_log, const float* __restrict__ D_param)
{
    int tid  = threadIdx.x;
    int w    = tid >> 5;
    int lane = tid & 31;
    int grp  = lane >> 4;
    int n    = lane & 15;
    int ch   = blockIdx.x * 16 + w * 2 + grp;   // 0..4095
    int b    = ch >> 11;
    int d    = ch & (DI - 1);

    float An = -expf(A_log[d * DS + n]);
    float Dp = D_param[d];

    const float* sp  = g_ssmp + (size_t)b * TT * NP;
    const float* dtp = g_dt   + (size_t)b * TT * DI + d;
    const float* xp  = g_xc   + (size_t)b * TT * DI + d;
    const float* zp  = g_xz   + (size_t)b * TT * (2*DI) + DI + d;
    __nv_bfloat16* yp = g_ybf + (size_t)b * TT * DI + d;

    float h = 0.f;
    float Bn  = sp[1 + n];
    float Cn  = sp[17 + n];
    float dtv = dtp[0];
    float xv  = xp[0];

    for (int t = 0; t < TT; t++) {
        float Bn2 = 0.f, Cn2 = 0.f, dt2 = 0.f, x2 = 0.f;
        if (t + 1 < TT) {
            Bn2 = sp[(size_t)(t+1)*NP + 1 + n];
            Cn2 = sp[(size_t)(t+1)*NP + 17 + n];
            dt2 = dtp[(size_t)(t+1)*DI];
            x2  = xp [(size_t)(t+1)*DI];
        }
        float ab = __expf(dtv * An);
        h = ab * h + (dtv * xv) * Bn;
        float p = h * Cn;
        p += __shfl_xor_sync(0xFFFFFFFFu, p, 1);
        p += __shfl_xor_sync(0xFFFFFFFFu, p, 2);
        p += __shfl_xor_sync(0xFFFFFFFFu, p, 4);
        p += __shfl_xor_sync(0xFFFFFFFFu, p, 8);
        if (n == 0) {
            float zv = zp[(size_t)t * (2*DI)];
            float yv = p + Dp * xv;
            yv *= zv / (1.f + __expf(-zv));
            yp[(size_t)t * DI] = __float2bfloat16(yv);
        }
        Bn = Bn2; Cn = Cn2; dtv = dt2; xv = x2;
    }
}

// ---------------- launch ----------------------------------------------------
extern "C" void kernel_launch(void* const* d_in, const int* in_sizes, int n_in,
                              void* d_out, int out_size)
{
    const float* x       = (const float*)d_in[0];
    const float* ln_g    = (const float*)d_in[1];
    const float* ln_b    = (const float*)d_in[2];
    const float* W_in    = (const float*)d_in[3];
    const float* conv_w  = (const float*)d_in[4];
    const float* conv_b  = (const float*)d_in[5];
    const float* W_x     = (const float*)d_in[6];
    const float* w_dt    = (const float*)d_in[7];
    const float* b_dt    = (const float*)d_in[8];
    const float* A_log   = (const float*)d_in[9];
    const float* D_param = (const float*)d_in[10];
    const float* W_out   = (const float*)d_in[11];
    float* out = (float*)d_out;

    float *xz;
    __nv_bfloat16 *xnb, *winb, *ybf, *woutb;
    cudaGetSymbolAddress((void**)&xz,    g_xz);
    cudaGetSymbolAddress((void**)&xnb,   g_xnb);
    cudaGetSymbolAddress((void**)&winb,  g_winb);
    cudaGetSymbolAddress((void**)&ybf,   g_ybf);
    cudaGetSymbolAddress((void**)&woutb, g_woutb);

    cudaFuncSetAttribute(gemm_bf16_mma,
                         cudaFuncAttributeMaxDynamicSharedMemorySize,
                         GEMM_SMEM_BYTES);

    // weight conversions (bf16)
    f2bf4<<<(2*DI*DM/4 + 255)/256, 256>>>(W_in,  winb,  2*DI*DM/4);
    f2bf4<<<(DM*DI/4   + 255)/256, 256>>>(W_out, woutb, DM*DI/4);

    // 1) layernorm -> bf16 xn
    ln_kernel<<<MR, 256>>>(x, ln_g, ln_b);

    // 2) xz = xn @ W_in.T   (M=2048, N=4096, K=1024) — bf16 mma.sync
    {
        dim3 grid(4096/128, 2048/128);
        gemm_bf16_mma<<<grid, 256, GEMM_SMEM_BYTES>>>(xnb, winb, nullptr, xz, 2*DI, DM);
    }

    // 3) causal conv + silu -> xc
    conv_silu_kernel<<<(MR*DI)/256, 256>>>(conv_w, conv_b);

    // 4) ssm_p = xc @ W_x.T
    proj_kernel<<<MR/2, 256>>>(W_x);

    // 5) dt = softplus(...)
    dt_kernel<<<(MR*DI)/256, 256>>>(w_dt, b_dt);

    // 6) selective scan -> y (gated, bf16)
    scan_kernel<<<(NB*DI)/16, 256>>>(A_log, D_param);

    // 7) out = x + y @ W_out.T   (M=2048, N=1024, K=2048) — bf16 mma.sync
    {
        dim3 grid(1024/128, 2048/128);
        gemm_bf16_mma<<<grid, 256, GEMM_SMEM_BYTES>>>(ybf, woutb, x, out, DM, DI);
    }
}

// round 7
// speedup vs baseline: 4.2550x; 2.2609x over previous
#include <cuda_runtime.h>
#include <cuda_bf16.h>
#include <math.h>
#include <stdint.h>

#define DM 1024      // D_MODEL
#define DI 2048      // D_INNER
#define DS 16        // D_STATE
#define NB 2         // batch
#define TT 1024      // seq len
#define MR (NB*TT)   // 2048 rows
#define NP (2*DS+1)  // 33

// ---------------- scratch (device globals; no allocations allowed) ----------
static __device__ float g_xz  [MR*2*DI];         // 32 MB fp32 (conv in + z gate)
static __device__ float g_xc  [MR*DI];           // [row][d] for proj
static __device__ float g_xct [NB*DI*TT];        // [ch][t] t-major for scan
static __device__ float g_ssmp[MR*NP];
static __device__ float g_dtt [NB*DI*TT];        // softplus dt, [ch][t] t-major
static __device__ __nv_bfloat16 g_xnb [MR*DM];   // LN output, bf16 (GEMM1 A)
static __device__ __nv_bfloat16 g_winb[2*DI*DM]; // W_in bf16   (GEMM1 B)
static __device__ __nv_bfloat16 g_ybf [MR*DI];   // gated scan out bf16 (GEMM2 A)
static __device__ __nv_bfloat16 g_woutb[DM*DI];  // W_out bf16  (GEMM2 B)

__device__ __forceinline__ uint32_t smem_to_u32(const void* p) {
    uint32_t a;
    asm("{ .reg .u64 t; cvta.to.shared.u64 t, %1; cvt.u32.u64 %0, t; }"
        : "=r"(a) : "l"(p));
    return a;
}
#define SWZ128(x) ((x) ^ (((x) >> 3) & 0x70))

// =================== bf16 mma.sync GEMM NT: C = A @ B^T (+Cadd) =============
#define GEMM_SMEM_BYTES (2 * 2 * 16384)

__global__ __launch_bounds__(256)
void gemm_bf16_mma(const __nv_bfloat16* __restrict__ A,
                   const __nv_bfloat16* __restrict__ B,
                   const float* __restrict__ Cadd, float* __restrict__ C,
                   int N, int K)
{
    extern __shared__ char dsm[];
    uint32_t sb = smem_to_u32(dsm);
    const int tid = threadIdx.x, wid = tid >> 5, lane = tid & 31;
    const int bm = blockIdx.y * 128, bn = blockIdx.x * 128;
    const int wm = wid >> 2, wn = wid & 3;
    const int mbase = wm * 64, nbase = wn * 32;

    const char* Ab = (const char*)A;
    const char* Bb = (const char*)B;
    const size_t K2 = (size_t)K * 2;
    const int KC = K >> 6;

    const int a_row = lane & 15;
    const int a_kc  = lane >> 4;
    const int b_row = ((lane >> 4) << 3) + (lane & 7);
    const int b_kc  = (lane >> 3) & 1;

    float d[4][4][4];
    #pragma unroll
    for (int i = 0; i < 4; i++)
        #pragma unroll
        for (int j = 0; j < 4; j++)
            { d[i][j][0]=0.f; d[i][j][1]=0.f; d[i][j][2]=0.f; d[i][j][3]=0.f; }

    #pragma unroll
    for (int it = 0; it < 8; it++) {
        int i = tid + it * 256;
        int isB = i >> 10;
        int j = i & 1023;
        int row = j >> 3, sub = j & 7;
        const char* src = (isB ? Bb + (size_t)(bn + row) * K2
                               : Ab + (size_t)(bm + row) * K2) + sub * 16;
        uint32_t dst = sb + isB * 16384 + SWZ128(row * 128 + sub * 16);
        asm volatile("cp.async.cg.shared.global [%0], [%1], 16;\n" :: "r"(dst), "l"(src));
    }
    asm volatile("cp.async.commit_group;\n" ::: "memory");

    for (int kc = 0; kc < KC; kc++) {
        int cur = kc & 1;
        if (kc + 1 < KC) {
            int nxt = (kc + 1) & 1;
            #pragma unroll
            for (int it = 0; it < 8; it++) {
                int i = tid + it * 256;
                int isB = i >> 10;
                int j = i & 1023;
                int row = j >> 3, sub = j & 7;
                const char* src = (isB ? Bb + (size_t)(bn + row) * K2
                                       : Ab + (size_t)(bm + row) * K2)
                                  + (size_t)(kc + 1) * 128 + sub * 16;
                uint32_t dst = sb + nxt * 32768 + isB * 16384
                             + SWZ128(row * 128 + sub * 16);
                asm volatile("cp.async.cg.shared.global [%0], [%1], 16;\n" :: "r"(dst), "l"(src));
            }
            asm volatile("cp.async.commit_group;\n" ::: "memory");
            asm volatile("cp.async.wait_group 1;\n" ::: "memory");
        } else {
            asm volatile("cp.async.wait_group 0;\n" ::: "memory");
        }
        __syncthreads();

        uint32_t sA = sb + cur * 32768;
        uint32_t sB = sA + 16384;

        #pragma unroll
        for (int ks = 0; ks < 4; ks++) {
            uint32_t a[4][4], b[4][2];
            #pragma unroll
            for (int mf = 0; mf < 4; mf++) {
                uint32_t addr = sA + SWZ128((mbase + mf*16 + a_row) * 128
                                            + (ks*2 + a_kc) * 16);
                asm volatile("ldmatrix.sync.aligned.m8n8.x4.shared.b16 {%0,%1,%2,%3}, [%4];"
                    : "=r"(a[mf][0]), "=r"(a[mf][1]), "=r"(a[mf][2]), "=r"(a[mf][3])
                    : "r"(addr));
            }
            #pragma unroll
            for (int nb2 = 0; nb2 < 2; nb2++) {
                uint32_t addr = sB + SWZ128((nbase + nb2*16 + b_row) * 128
                                            + (ks*2 + b_kc) * 16);
                asm volatile("ldmatrix.sync.aligned.m8n8.x4.shared.b16 {%0,%1,%2,%3}, [%4];"
                    : "=r"(b[nb2*2][0]), "=r"(b[nb2*2][1]),
                      "=r"(b[nb2*2+1][0]), "=r"(b[nb2*2+1][1])
                    : "r"(addr));
            }
            #pragma unroll
            for (int mf = 0; mf < 4; mf++)
                #pragma unroll
                for (int nf = 0; nf < 4; nf++) {
                    asm volatile(
                        "mma.sync.aligned.m16n8k16.row.col.f32.bf16.bf16.f32 "
                        "{%0,%1,%2,%3}, {%4,%5,%6,%7}, {%8,%9}, {%0,%1,%2,%3};"
                        : "+f"(d[mf][nf][0]), "+f"(d[mf][nf][1]),
                          "+f"(d[mf][nf][2]), "+f"(d[mf][nf][3])
                        : "r"(a[mf][0]), "r"(a[mf][1]), "r"(a[mf][2]), "r"(a[mf][3]),
                          "r"(b[nf][0]), "r"(b[nf][1]));
                }
        }
        __syncthreads();
    }

    const int er = lane >> 2;
    const int ec = (lane & 3) * 2;
    #pragma unroll
    for (int mf = 0; mf < 4; mf++) {
        int m0 = bm + mbase + mf*16 + er;
        #pragma unroll
        for (int nf = 0; nf < 4; nf++) {
            int col = bn + nbase + nf*8 + ec;
            float2 v0 = make_float2(d[mf][nf][0], d[mf][nf][1]);
            float2 v1 = make_float2(d[mf][nf][2], d[mf][nf][3]);
            if (Cadd) {
                float2 c0 = *(const float2*)(Cadd + (size_t)m0 * N + col);
                float2 c1 = *(const float2*)(Cadd + (size_t)(m0+8) * N + col);
                v0.x += c0.x; v0.y += c0.y; v1.x += c1.x; v1.y += c1.y;
            }
            *(float2*)(C + (size_t)m0 * N + col) = v0;
            *(float2*)(C + (size_t)(m0+8) * N + col) = v1;
        }
    }
}

// ---------------- fp32 -> bf16 convert (vectorized x4) ----------------------
__global__ __launch_bounds__(256) void f2bf4(
    const float* __restrict__ in, __nv_bfloat16* __restrict__ out, int n4)
{
    int i = blockIdx.x * 256 + threadIdx.x;
    if (i >= n4) return;
    float4 v = ((const float4*)in)[i];
    ((__nv_bfloat162*)out)[i*2+0] = __floats2bfloat162_rn(v.x, v.y);
    ((__nv_bfloat162*)out)[i*2+1] = __floats2bfloat162_rn(v.z, v.w);
}

// ---------------- LayerNorm: one block per row, bf16 output -----------------
__global__ __launch_bounds__(256) void ln_kernel(
    const float* __restrict__ x, const float* __restrict__ gamma,
    const float* __restrict__ beta)
{
    int row = blockIdx.x;
    int tid = threadIdx.x;
    const float4* xr = (const float4*)(x + (size_t)row * DM);
    float4 v = xr[tid];
    float s = v.x + v.y + v.z + v.w;
    float q = v.x*v.x + v.y*v.y + v.z*v.z + v.w*v.w;
    #pragma unroll
    for (int o = 16; o; o >>= 1) {
        s += __shfl_down_sync(0xFFFFFFFFu, s, o);
        q += __shfl_down_sync(0xFFFFFFFFu, q, o);
    }
    __shared__ float ss[8], sq[8];
    __shared__ float mu_s, rs_s;
    if ((tid & 31) == 0) { ss[tid >> 5] = s; sq[tid >> 5] = q; }
    __syncthreads();
    if (tid == 0) {
        float S = 0.f, Q = 0.f;
        #pragma unroll
        for (int i = 0; i < 8; i++) { S += ss[i]; Q += sq[i]; }
        float mu  = S / (float)DM;
        float var = Q / (float)DM - mu * mu;
        mu_s = mu;
        rs_s = rsqrtf(var + 1e-5f);
    }
    __syncthreads();
    float mu = mu_s, rs = rs_s;
    float4 g = ((const float4*)gamma)[tid];
    float4 b = ((const float4*)beta)[tid];
    float ox = (v.x - mu) * rs * g.x + b.x;
    float oy = (v.y - mu) * rs * g.y + b.y;
    float oz = (v.z - mu) * rs * g.z + b.z;
    float ow = (v.w - mu) * rs * g.w + b.w;
    __nv_bfloat162* o2 = (__nv_bfloat162*)(g_xnb + (size_t)row * DM);
    o2[tid*2+0] = __floats2bfloat162_rn(ox, oy);
    o2[tid*2+1] = __floats2bfloat162_rn(oz, ow);
}

// ------- causal conv (k=4) + bias + SiLU, dual-layout output ----------------
// Tile: 32 d x 64 t. Writes g_xc [row][d] and g_xct [ch][t] (smem transpose).
__global__ __launch_bounds__(256) void conv_silu_kernel(
    const float* __restrict__ cw, const float* __restrict__ cb)
{
    __shared__ float xs[67][32];      // t0-3 .. t0+63
    __shared__ float ys[64][33];      // padded for transpose
    int t0 = blockIdx.x * 64;         // global row tile (never straddles batch)
    int d0 = blockIdx.y * 32;
    int tid = threadIdx.x;
    int col = tid & 31, r0 = tid >> 5;

    bool interior = (t0 & (TT - 1)) != 0;   // t0-3..t0-1 in same batch?
    for (int r = r0; r < 67; r += 8) {
        int t = t0 + r - 3;
        float v = 0.f;
        if (r >= 3 || interior)
            v = g_xz[(size_t)t * (2*DI) + d0 + col];
        xs[r][col] = v;
    }
    __syncthreads();

    float w0 = cw[(d0+col)*4+0], w1 = cw[(d0+col)*4+1];
    float w2 = cw[(d0+col)*4+2], w3 = cw[(d0+col)*4+3];
    float bias = cb[d0+col];
    #pragma unroll
    for (int tl = r0; tl < 64; tl += 8) {
        float acc = bias + w3*xs[tl+3][col] + w2*xs[tl+2][col]
                         + w1*xs[tl+1][col] + w0*xs[tl][col];
        acc = acc / (1.f + __expf(-acc));
        g_xc[(size_t)(t0+tl) * DI + d0 + col] = acc;
        ys[tl][col] = acc;
    }
    __syncthreads();

    // transposed write: [ch][t], coalesced along t
    int b = t0 >> 10;
    int tin = t0 & (TT - 1);
    for (int i = tid; i < 32*64; i += 256) {
        int dd = i >> 6, tc = i & 63;
        g_xct[(size_t)(b*DI + d0 + dd) * TT + tin + tc] = ys[tc][dd];
    }
}

// ---------------- ssm_p = xc @ W_x.T  (N=33), 2 rows per block --------------
__global__ __launch_bounds__(256) void proj_kernel(const float* __restrict__ Wx)
{
    int row0 = blockIdx.x * 2;
    const float* x0 = g_xc + (size_t)row0 * DI;
    const float* x1 = x0 + DI;
    float a0[NP], a1[NP];
    #pragma unroll
    for (int n = 0; n < NP; n++) { a0[n] = 0.f; a1[n] = 0.f; }
    for (int k = threadIdx.x; k < DI; k += 256) {
        float v0 = x0[k], v1 = x1[k];
        #pragma unroll
        for (int n = 0; n < NP; n++) {
            float wv = Wx[(size_t)n * DI + k];
            a0[n] += v0 * wv;
            a1[n] += v1 * wv;
        }
    }
    #pragma unroll
    for (int n = 0; n < NP; n++) {
        #pragma unroll
        for (int o = 16; o; o >>= 1) {
            a0[n] += __shfl_down_sync(0xFFFFFFFFu, a0[n], o);
            a1[n] += __shfl_down_sync(0xFFFFFFFFu, a1[n], o);
        }
    }
    __shared__ float red0[8][NP], red1[8][NP];
    int w = threadIdx.x >> 5, l = threadIdx.x & 31;
    if (l == 0) {
        #pragma unroll
        for (int n = 0; n < NP; n++) { red0[w][n] = a0[n]; red1[w][n] = a1[n]; }
    }
    __syncthreads();
    if (threadIdx.x < NP) {
        float s0 = 0.f, s1 = 0.f;
        #pragma unroll
        for (int ww = 0; ww < 8; ww++) { s0 += red0[ww][threadIdx.x]; s1 += red1[ww][threadIdx.x]; }
        g_ssmp[(size_t)row0 * NP + threadIdx.x] = s0;
        g_ssmp[(size_t)(row0+1) * NP + threadIdx.x] = s1;
    }
}

// -------- dt = softplus(dt_raw*w_dt + b_dt), written t-major [ch][t] --------
__global__ __launch_bounds__(256) void dt_kernel(
    const float* __restrict__ w_dt, const float* __restrict__ b_dt)
{
    int idx = blockIdx.x * 256 + threadIdx.x;   // over NB*DI*TT, t fastest
    int ch = idx >> 10;
    int t  = idx & (TT - 1);
    int b  = ch >> 11;
    int d  = ch & (DI - 1);
    float v = g_ssmp[(size_t)(b*TT + t) * NP] * w_dt[d] + b_dt[d];
    g_dtt[idx] = (v > 15.f) ? v : log1pf(__expf(v));
}

// ---------------- selective scan, t-major inputs, chunked by 16 -------------
// warp = 2 channels x 16 states; block = 16 channels; fused gate in flush.
__global__ __launch_bounds__(256) void scan_kernel(
    const float* __restrict__ A_log, const float* __restrict__ D_param)
{
    __shared__ float y_s[64][16];   // [t_local][ch_local]
    int tid  = threadIdx.x;
    int w    = tid >> 5;
    int lane = tid & 31;
    int grp  = lane >> 4;
    int n    = lane & 15;
    int chl  = w * 2 + grp;
    int ch   = blockIdx.x * 16 + chl;       // 0..4095
    int b    = ch >> 11;
    int d    = ch & (DI - 1);

    float An = -__expf(A_log[d * DS + n]);
    float Dp = D_param[d];

    const float*  sp   = g_ssmp + (size_t)b * TT * NP;
    const float4* dtp4 = (const float4*)(g_dtt + (size_t)ch * TT);
    const float4* xcp4 = (const float4*)(g_xct + (size_t)ch * TT);

    // flush-phase mapping
    int fdl = tid & 15, ftl0 = tid >> 4;
    int bB  = (blockIdx.x * 16) >> 11;
    int d0  = (blockIdx.x * 16) & (DI - 1);

    float h = 0.f;
    for (int c = 0; c < TT/16; c++) {
        float4 dt4[4], xc4[4];
        #pragma unroll
        for (int i = 0; i < 4; i++) { dt4[i] = dtp4[c*4+i]; xc4[i] = xcp4[c*4+i]; }
        float Bv[16], Cv[16];
        #pragma unroll
        for (int j = 0; j < 16; j++) {
            const float* row = sp + (size_t)(c*16 + j) * NP;
            Bv[j] = row[1 + n];
            Cv[j] = row[17 + n];
        }
        const float* dts = (const float*)dt4;
        const float* xcs = (const float*)xc4;
        #pragma unroll
        for (int j = 0; j < 16; j++) {
            float dtv = dts[j];
            float xv  = xcs[j];
            float ab  = __expf(dtv * An);
            h = ab * h + (dtv * xv) * Bv[j];
            float p = h * Cv[j];
            p += __shfl_xor_sync(0xFFFFFFFFu, p, 1);
            p += __shfl_xor_sync(0xFFFFFFFFu, p, 2);
            p += __shfl_xor_sync(0xFFFFFFFFu, p, 4);
            p += __shfl_xor_sync(0xFFFFFFFFu, p, 8);
            if (n == 0) y_s[(c & 3) * 16 + j][chl] = p + Dp * xv;
        }
        if ((c & 3) == 3) {
            __syncthreads();
            int tbase = (c - 3) * 16;
            #pragma unroll
            for (int pass = 0; pass < 4; pass++) {
                int tl = ftl0 + pass * 16;
                int t  = tbase + tl;
                size_t row = (size_t)(bB * TT + t);
                float zv = g_xz[row * (2*DI) + DI + d0 + fdl];
                float yp = y_s[tl][fdl];
                float gate = zv / (1.f + __expf(-zv));
                g_ybf[row * DI + d0 + fdl] = __float2bfloat16(yp * gate);
            }
            __syncthreads();
        }
    }
}

// ---------------- launch ----------------------------------------------------
extern "C" void kernel_launch(void* const* d_in, const int* in_sizes, int n_in,
                              void* d_out, int out_size)
{
    const float* x       = (const float*)d_in[0];
    const float* ln_g    = (const float*)d_in[1];
    const float* ln_b    = (const float*)d_in[2];
    const float* W_in    = (const float*)d_in[3];
    const float* conv_w  = (const float*)d_in[4];
    const float* conv_b  = (const float*)d_in[5];
    const float* W_x     = (const float*)d_in[6];
    const float* w_dt    = (const float*)d_in[7];
    const float* b_dt    = (const float*)d_in[8];
    const float* A_log   = (const float*)d_in[9];
    const float* D_param = (const float*)d_in[10];
    const float* W_out   = (const float*)d_in[11];
    float* out = (float*)d_out;

    float *xz;
    __nv_bfloat16 *xnb, *winb, *ybf, *woutb;
    cudaGetSymbolAddress((void**)&xz,    g_xz);
    cudaGetSymbolAddress((void**)&xnb,   g_xnb);
    cudaGetSymbolAddress((void**)&winb,  g_winb);
    cudaGetSymbolAddress((void**)&ybf,   g_ybf);
    cudaGetSymbolAddress((void**)&woutb, g_woutb);

    cudaFuncSetAttribute(gemm_bf16_mma,
                         cudaFuncAttributeMaxDynamicSharedMemorySize,
                         GEMM_SMEM_BYTES);

    // weight conversions (bf16)
    f2bf4<<<(2*DI*DM/4 + 255)/256, 256>>>(W_in,  winb,  2*DI*DM/4);
    f2bf4<<<(DM*DI/4   + 255)/256, 256>>>(W_out, woutb, DM*DI/4);

    // 1) layernorm -> bf16 xn
    ln_kernel<<<MR, 256>>>(x, ln_g, ln_b);

    // 2) xz = xn @ W_in.T   (M=2048, N=4096, K=1024)
    {
        dim3 grid(4096/128, 2048/128);
        gemm_bf16_mma<<<grid, 256, GEMM_SMEM_BYTES>>>(xnb, winb, nullptr, xz, 2*DI, DM);
    }

    // 3) causal conv + silu -> xc [row][d] and xct [ch][t]
    {
        dim3 grid(MR/64, DI/32);
        conv_silu_kernel<<<grid, 256>>>(conv_w, conv_b);
    }

    // 4) ssm_p = xc @ W_x.T
    proj_kernel<<<MR/2, 256>>>(W_x);

    // 5) dt = softplus(...) -> [ch][t]
    dt_kernel<<<(NB*DI*TT)/256, 256>>>(w_dt, b_dt);

    // 6) selective scan (fused gate) -> ybf
    scan_kernel<<<(NB*DI)/16, 256>>>(A_log, D_param);

    // 7) out = x + y @ W_out.T   (M=2048, N=1024, K=2048)
    {
        dim3 grid(1024/128, 2048/128);
        gemm_bf16_mma<<<grid, 256, GEMM_SMEM_BYTES>>>(ybf, woutb, x, out, DM, DI);
    }
}